// round 3
// baseline (speedup 1.0000x reference)
#include <cuda_runtime.h>
#include <cuda_bf16.h>
#include <cstdint>

#define B_ 4
#define C_ 16
#define H_ 512
#define W_ 512
#define HW_ (H_ * W_)            // 262144
#define NPIX_ (B_ * HW_)         // 1048576
#define EPS_ 1e-10f

// Scratch: packed (priority<<32 | float_bits(Z)) per output pixel. 8 MB.
// Zero at module load; final_kernel re-zeros after consuming, so every
// graph replay starts from identical state.
__device__ unsigned long long g_scratch[NPIX_];

// ---------------------------------------------------------------------------
// Main: unproject -> last-mask transform -> reproject -> priority scatter.
// 4 pixels per thread; mask channels scanned in groups of 4 (MLP=4).
// ---------------------------------------------------------------------------
__global__ void __launch_bounds__(256, 8)
main_kernel(const float* __restrict__ depth,
            const float* __restrict__ K,
            const float* __restrict__ T,
            const void* __restrict__ masks) {
    __shared__ float sT[C_ * 16];
    __shared__ float sK[9];
    __shared__ float sKi[9];
    __shared__ int   s_bad;

    const int tid  = threadIdx.x;
    const int base = blockIdx.x * 1024;
    const int b    = base >> 18;               // batch (constant per block)

    if (tid == 0) {
        s_bad = 0;
        const float* k = K + b * 9;
        float a = k[0], bb = k[1], c = k[2];
        float d = k[3], e  = k[4], f = k[5];
        float g = k[6], h  = k[7], i = k[8];
        float A  =  (e * i - f * h);
        float Bc = -(d * i - f * g);
        float Cc =  (d * h - e * g);
        float det = a * A + bb * Bc + c * Cc;
        float inv = 1.0f / det;
        sKi[0] = A * inv;
        sKi[1] = -(bb * i - c * h) * inv;
        sKi[2] =  (bb * f - c * e) * inv;
        sKi[3] = Bc * inv;
        sKi[4] =  (a * i - c * g) * inv;
        sKi[5] = -(a * f - c * d) * inv;
        sKi[6] = Cc * inv;
        sKi[7] = -(a * h - bb * g) * inv;
        sKi[8] =  (a * e - bb * d) * inv;
    }
    sT[tid] = T[b * (C_ * 16) + tid];
    if (tid < 9) sK[tid] = K[b * 9 + tid];
    __syncthreads();

    // Mask dtype sniff: 128 threads read first 512 bytes as u32.
    if (tid < 128) {
        unsigned wv = ((const unsigned*)masks)[tid];
        if (wv > 1u) atomicOr(&s_bad, 1);
    }
    __syncthreads();
    const bool mask_is_i32 = (s_bad == 0);

    const int idx = base + tid * 4;
    const int rem = idx & (HW_ - 1);
    const int v   = rem >> 9;
    const int u   = rem & (W_ - 1);

    const float4 d4 = *(const float4*)(depth + idx);
    const float  dd[4] = {d4.x, d4.y, d4.z, d4.w};

    // Last set channel per pixel; scan 4 channels per round, loads batched.
    const long mbase = (long)b * (C_ * HW_) + rem;
    int cw[4] = {-1, -1, -1, -1};
    if (mask_is_i32) {
        const int* m = (const int*)masks;
        #pragma unroll 1
        for (int g = 0; g < 4; ++g) {
            const int cb = 12 - 4 * g;
            const int4 a3 = __ldg((const int4*)(m + mbase + (long)(cb + 3) * HW_));
            const int4 a2 = __ldg((const int4*)(m + mbase + (long)(cb + 2) * HW_));
            const int4 a1 = __ldg((const int4*)(m + mbase + (long)(cb + 1) * HW_));
            const int4 a0 = __ldg((const int4*)(m + mbase + (long)(cb + 0) * HW_));
            if (cw[0] < 0) cw[0] = a3.x ? cb+3 : a2.x ? cb+2 : a1.x ? cb+1 : a0.x ? cb : -1;
            if (cw[1] < 0) cw[1] = a3.y ? cb+3 : a2.y ? cb+2 : a1.y ? cb+1 : a0.y ? cb : -1;
            if (cw[2] < 0) cw[2] = a3.z ? cb+3 : a2.z ? cb+2 : a1.z ? cb+1 : a0.z ? cb : -1;
            if (cw[3] < 0) cw[3] = a3.w ? cb+3 : a2.w ? cb+2 : a1.w ? cb+1 : a0.w ? cb : -1;
            if ((cw[0] | cw[1] | cw[2] | cw[3]) >= 0) break;
        }
    } else {
        const unsigned char* mb = (const unsigned char*)masks;
        #pragma unroll 1
        for (int g = 0; g < 4; ++g) {
            const int cb = 12 - 4 * g;
            const unsigned a3 = __ldg((const unsigned*)(mb + mbase + (long)(cb + 3) * HW_));
            const unsigned a2 = __ldg((const unsigned*)(mb + mbase + (long)(cb + 2) * HW_));
            const unsigned a1 = __ldg((const unsigned*)(mb + mbase + (long)(cb + 1) * HW_));
            const unsigned a0 = __ldg((const unsigned*)(mb + mbase + (long)(cb + 0) * HW_));
            #pragma unroll
            for (int p = 0; p < 4; ++p) {
                const unsigned lane = 0xffu << (8 * p);
                if (cw[p] < 0)
                    cw[p] = (a3 & lane) ? cb+3 : (a2 & lane) ? cb+2 :
                            (a1 & lane) ? cb+1 : (a0 & lane) ? cb : -1;
            }
            if ((cw[0] | cw[1] | cw[2] | cw[3]) >= 0) break;
        }
    }

    const float vf = (float)v;
    #pragma unroll
    for (int p = 0; p < 4; ++p) {
        const float uf = (float)(u + p);
        const float d  = dd[p];

        float x = (sKi[0] * uf + sKi[1] * vf + sKi[2]) * d;
        float y = (sKi[3] * uf + sKi[4] * vf + sKi[5]) * d;
        float z = (sKi[6] * uf + sKi[7] * vf + sKi[8]) * d;

        const int c = cw[p];
        if (c >= 0) {
            const float* Tm = &sT[c * 16];
            float tx = Tm[0]  * x + Tm[1]  * y + Tm[2]  * z + Tm[3];
            float ty = Tm[4]  * x + Tm[5]  * y + Tm[6]  * z + Tm[7];
            float tz = Tm[8]  * x + Tm[9]  * y + Tm[10] * z + Tm[11];
            float tw = Tm[12] * x + Tm[13] * y + Tm[14] * z + Tm[15];
            float inv = 1.0f / (tw + EPS_);
            x = tx * inv;
            y = ty * inv;
            z = tz * inv;
        }

        float phx = sK[0] * x + sK[1] * y + sK[2] * z;
        float phy = sK[3] * x + sK[4] * y + sK[5] * z;
        float phz = sK[6] * x + sK[7] * y + sK[8] * z;
        float invz = 1.0f / (phz + EPS_);
        float px = phx * invz;
        float py = phy * invz;

        int ui = (int)fminf(fmaxf(px, 0.0f), (float)(W_ - 1));
        int vi = (int)fminf(fmaxf(py, 0.0f), (float)(H_ - 1));

        unsigned long long pkt =
            ((unsigned long long)(unsigned)(rem + p + 1) << 32) |
            (unsigned long long)__float_as_uint(z);
        atomicMax(&g_scratch[b * HW_ + vi * W_ + ui], pkt);
    }
}

// ---------------------------------------------------------------------------
// Final: resolve scatter else passthrough depth; re-zero scratch.
// 16 px/thread, 12 front-batched LDG.128.
// ---------------------------------------------------------------------------
__global__ void __launch_bounds__(256)
final_kernel(const float* __restrict__ depth,
             float* __restrict__ out) {
    const int base = (blockIdx.x * 256 + threadIdx.x) * 16;

    ulonglong2 s[8];
    float4 dp[4];
    #pragma unroll
    for (int i = 0; i < 8; ++i) s[i] = *(ulonglong2*)&g_scratch[base + 2 * i];
    #pragma unroll
    for (int i = 0; i < 4; ++i) dp[i] = *(const float4*)(depth + base + 4 * i);

    #pragma unroll
    for (int i = 0; i < 4; ++i) {
        float4 o;
        o.x = s[2*i].x     ? __uint_as_float((unsigned)s[2*i].x)     : dp[i].x;
        o.y = s[2*i].y     ? __uint_as_float((unsigned)s[2*i].y)     : dp[i].y;
        o.z = s[2*i + 1].x ? __uint_as_float((unsigned)s[2*i + 1].x) : dp[i].z;
        o.w = s[2*i + 1].y ? __uint_as_float((unsigned)s[2*i + 1].y) : dp[i].w;
        *(float4*)(out + base + 4 * i) = o;
    }

    const ulonglong2 zz = {0ull, 0ull};
    #pragma unroll
    for (int i = 0; i < 8; ++i) *(ulonglong2*)&g_scratch[base + 2 * i] = zz;
}

extern "C" void kernel_launch(void* const* d_in, const int* in_sizes, int n_in,
                              void* d_out, int out_size) {
    const float* depth = (const float*)d_in[0];
    const float* K     = (const float*)d_in[1];
    const float* T     = (const float*)d_in[2];
    const void*  masks = d_in[3];
    float* out = (float*)d_out;

    main_kernel<<<NPIX_ / 1024, 256>>>(depth, K, T, masks);
    final_kernel<<<NPIX_ / 4096, 256>>>(depth, out);
}

// round 4
// speedup vs baseline: 1.0097x; 1.0097x over previous
#include <cuda_runtime.h>
#include <cuda_bf16.h>
#include <cstdint>

#define B_ 4
#define C_ 16
#define H_ 512
#define W_ 512
#define HW_ (H_ * W_)            // 262144
#define NPIX_ (B_ * HW_)         // 1048576
#define EPS_ 1e-10f

#define NBLK_ 512
#define NTHR_ 256
#define HALF_ (NPIX_ / 2)        // 524288 px per grid-stride iteration

// Scratch: packed (priority<<32 | float_bits(Z)) per output pixel. 8 MB.
// Zero at module load; phase 2 re-zeros after consuming -> replay-safe.
__device__ unsigned long long g_scratch[NPIX_];
// Monotonic grid-barrier ticket counter (never reset; replay-safe).
__device__ unsigned g_bar;

__device__ __forceinline__ void invert3x3(const float* k, float* o) {
    float a = k[0], bb = k[1], c = k[2];
    float d = k[3], e  = k[4], f = k[5];
    float g = k[6], h  = k[7], i = k[8];
    float A  =  (e * i - f * h);
    float Bc = -(d * i - f * g);
    float Cc =  (d * h - e * g);
    float det = a * A + bb * Bc + c * Cc;
    float inv = 1.0f / det;
    o[0] = A * inv;
    o[1] = -(bb * i - c * h) * inv;
    o[2] =  (bb * f - c * e) * inv;
    o[3] = Bc * inv;
    o[4] =  (a * i - c * g) * inv;
    o[5] = -(a * f - c * d) * inv;
    o[6] = Cc * inv;
    o[7] = -(a * h - bb * g) * inv;
    o[8] =  (a * e - bb * d) * inv;
}

// ---------------------------------------------------------------------------
// Fused: phase 1 scatter -> grid barrier -> phase 2 resolve + re-zero.
// 512 blocks x 256 threads; all blocks resident (occ>=4) so the software
// grid barrier is deadlock-free.
// ---------------------------------------------------------------------------
__global__ void __launch_bounds__(NTHR_, 4)
fused_kernel(const float* __restrict__ depth,
             const float* __restrict__ K,
             const float* __restrict__ T,
             const void* __restrict__ masks,
             float* __restrict__ out) {
    // Shared tiles for the block's TWO batches (iter0: b, iter1: b+2).
    __shared__ float sT[2][C_ * 16];
    __shared__ float sK[2][9];
    __shared__ float sKi[2][9];
    __shared__ int   s_bad;

    const int tid = threadIdx.x;
    const int px0 = (blockIdx.x * NTHR_ + tid) * 4;   // iter-0 first pixel
    const int b0  = px0 >> 18;                        // 0 or 1
    const int b1  = b0 + 2;                           // iter-1 batch

    if (tid == 0) {
        s_bad = 0;
        invert3x3(K + b0 * 9, sKi[0]);
        invert3x3(K + b1 * 9, sKi[1]);
    }
    sT[0][tid] = T[b0 * (C_ * 16) + tid];
    sT[1][tid] = T[b1 * (C_ * 16) + tid];
    if (tid < 9) {
        sK[0][tid] = K[b0 * 9 + tid];
        sK[1][tid] = K[b1 * 9 + tid];
    }
    // Mask dtype sniff: 128 threads read first 512 bytes as u32.
    if (tid >= 128 && tid < 256) {
        unsigned wv = ((const unsigned*)masks)[tid - 128];
        if (wv > 1u) atomicOr(&s_bad, 1);
    }
    __syncthreads();
    const bool mask_is_i32 = (s_bad == 0);

    // ---------------- Phase 1: scatter (2 iterations x 4 px) ----------------
    #pragma unroll
    for (int it = 0; it < 2; ++it) {
        const int idx = px0 + it * HALF_;
        const int b   = (it == 0) ? b0 : b1;
        const int rem = idx & (HW_ - 1);
        const int v   = rem >> 9;
        const int u   = rem & (W_ - 1);

        const float4 d4 = *(const float4*)(depth + idx);
        const float  dd[4] = {d4.x, d4.y, d4.z, d4.w};

        // Last set channel per pixel; 4 channels per round, loads batched.
        const long mbase = (long)b * (C_ * HW_) + rem;
        int cw[4] = {-1, -1, -1, -1};
        if (mask_is_i32) {
            const int* m = (const int*)masks;
            #pragma unroll 1
            for (int g = 0; g < 4; ++g) {
                const int cb = 12 - 4 * g;
                const int4 a3 = __ldg((const int4*)(m + mbase + (long)(cb + 3) * HW_));
                const int4 a2 = __ldg((const int4*)(m + mbase + (long)(cb + 2) * HW_));
                const int4 a1 = __ldg((const int4*)(m + mbase + (long)(cb + 1) * HW_));
                const int4 a0 = __ldg((const int4*)(m + mbase + (long)(cb + 0) * HW_));
                if (cw[0] < 0) cw[0] = a3.x ? cb+3 : a2.x ? cb+2 : a1.x ? cb+1 : a0.x ? cb : -1;
                if (cw[1] < 0) cw[1] = a3.y ? cb+3 : a2.y ? cb+2 : a1.y ? cb+1 : a0.y ? cb : -1;
                if (cw[2] < 0) cw[2] = a3.z ? cb+3 : a2.z ? cb+2 : a1.z ? cb+1 : a0.z ? cb : -1;
                if (cw[3] < 0) cw[3] = a3.w ? cb+3 : a2.w ? cb+2 : a1.w ? cb+1 : a0.w ? cb : -1;
                if ((cw[0] | cw[1] | cw[2] | cw[3]) >= 0) break;
            }
        } else {
            const unsigned char* mb = (const unsigned char*)masks;
            #pragma unroll 1
            for (int g = 0; g < 4; ++g) {
                const int cb = 12 - 4 * g;
                const unsigned a3 = __ldg((const unsigned*)(mb + mbase + (long)(cb + 3) * HW_));
                const unsigned a2 = __ldg((const unsigned*)(mb + mbase + (long)(cb + 2) * HW_));
                const unsigned a1 = __ldg((const unsigned*)(mb + mbase + (long)(cb + 1) * HW_));
                const unsigned a0 = __ldg((const unsigned*)(mb + mbase + (long)(cb + 0) * HW_));
                #pragma unroll
                for (int p = 0; p < 4; ++p) {
                    const unsigned lane = 0xffu << (8 * p);
                    if (cw[p] < 0)
                        cw[p] = (a3 & lane) ? cb+3 : (a2 & lane) ? cb+2 :
                                (a1 & lane) ? cb+1 : (a0 & lane) ? cb : -1;
                }
                if ((cw[0] | cw[1] | cw[2] | cw[3]) >= 0) break;
            }
        }

        const float vf = (float)v;
        #pragma unroll
        for (int p = 0; p < 4; ++p) {
            const float uf = (float)(u + p);
            const float d  = dd[p];

            float x = (sKi[it][0] * uf + sKi[it][1] * vf + sKi[it][2]) * d;
            float y = (sKi[it][3] * uf + sKi[it][4] * vf + sKi[it][5]) * d;
            float z = (sKi[it][6] * uf + sKi[it][7] * vf + sKi[it][8]) * d;

            const int c = cw[p];
            if (c >= 0) {
                const float* Tm = &sT[it][c * 16];
                float tx = Tm[0]  * x + Tm[1]  * y + Tm[2]  * z + Tm[3];
                float ty = Tm[4]  * x + Tm[5]  * y + Tm[6]  * z + Tm[7];
                float tz = Tm[8]  * x + Tm[9]  * y + Tm[10] * z + Tm[11];
                float tw = Tm[12] * x + Tm[13] * y + Tm[14] * z + Tm[15];
                float inv = 1.0f / (tw + EPS_);
                x = tx * inv;
                y = ty * inv;
                z = tz * inv;
            }

            float phx = sK[it][0] * x + sK[it][1] * y + sK[it][2] * z;
            float phy = sK[it][3] * x + sK[it][4] * y + sK[it][5] * z;
            float phz = sK[it][6] * x + sK[it][7] * y + sK[it][8] * z;
            float invz = 1.0f / (phz + EPS_);
            float px = phx * invz;
            float py = phy * invz;

            int ui = (int)fminf(fmaxf(px, 0.0f), (float)(W_ - 1));
            int vi = (int)fminf(fmaxf(py, 0.0f), (float)(H_ - 1));

            unsigned long long pkt =
                ((unsigned long long)(unsigned)(rem + p + 1) << 32) |
                (unsigned long long)__float_as_uint(z);
            atomicMax(&g_scratch[b * HW_ + vi * W_ + ui], pkt);
        }
    }

    // ---------------- Grid barrier (monotonic tickets; replay-safe) --------
    __threadfence();                 // make this block's atomics visible
    __syncthreads();                 // all threads in block done with phase 1
    if (tid == 0) {
        unsigned t      = atomicAdd(&g_bar, 1u);
        unsigned target = (t / NBLK_ + 1u) * NBLK_;
        while (*(volatile unsigned*)&g_bar < target) { /* spin */ }
    }
    __syncthreads();
    __threadfence();

    // ---------------- Phase 2: resolve + re-zero (8 px/thread) -------------
    const int base = (blockIdx.x * NTHR_ + tid) * 8;

    ulonglong2 s[4];
    float4 dp[2];
    #pragma unroll
    for (int i = 0; i < 4; ++i) s[i] = *(ulonglong2*)&g_scratch[base + 2 * i];
    #pragma unroll
    for (int i = 0; i < 2; ++i) dp[i] = *(const float4*)(depth + base + 4 * i);

    #pragma unroll
    for (int i = 0; i < 2; ++i) {
        float4 o;
        o.x = s[2*i].x     ? __uint_as_float((unsigned)s[2*i].x)     : dp[i].x;
        o.y = s[2*i].y     ? __uint_as_float((unsigned)s[2*i].y)     : dp[i].y;
        o.z = s[2*i + 1].x ? __uint_as_float((unsigned)s[2*i + 1].x) : dp[i].z;
        o.w = s[2*i + 1].y ? __uint_as_float((unsigned)s[2*i + 1].y) : dp[i].w;
        *(float4*)(out + base + 4 * i) = o;
    }

    const ulonglong2 zz = {0ull, 0ull};
    #pragma unroll
    for (int i = 0; i < 4; ++i) *(ulonglong2*)&g_scratch[base + 2 * i] = zz;
}

extern "C" void kernel_launch(void* const* d_in, const int* in_sizes, int n_in,
                              void* d_out, int out_size) {
    const float* depth = (const float*)d_in[0];
    const float* K     = (const float*)d_in[1];
    const float* T     = (const float*)d_in[2];
    const void*  masks = d_in[3];
    float* out = (float*)d_out;

    fused_kernel<<<NBLK_, NTHR_>>>(depth, K, T, masks, out);
}

// round 6
// speedup vs baseline: 1.2301x; 1.2183x over previous
#include <cuda_runtime.h>
#include <cuda_bf16.h>
#include <cstdint>

#define B_ 4
#define C_ 16
#define H_ 512
#define W_ 512
#define HW_ (H_ * W_)            // 262144
#define NPIX_ (B_ * HW_)         // 1048576
#define EPS_ 1e-10f

// Scratch: packed (priority<<32 | float_bits(Z)) per output pixel. 8 MB.
// Zero at module load; final_kernel re-zeros after consuming -> replay-safe.
__device__ unsigned long long g_scratch[NPIX_];

// ---------------------------------------------------------------------------
// Main: unproject -> last-mask transform -> reproject -> priority scatter.
// 4 px/thread. Mask scan: channels 15..8 front-batched (MLP=8); rare
// fallback batch for channels 7..0. Chain depth ~1 memory round-trip.
// ---------------------------------------------------------------------------
__global__ void __launch_bounds__(256)
main_kernel(const float* __restrict__ depth,
            const float* __restrict__ K,
            const float* __restrict__ T,
            const void* __restrict__ masks) {
    __shared__ float sT[C_ * 16];
    __shared__ float sK[9];
    __shared__ float sKi[9];
    __shared__ int   s_bad;

    const int tid  = threadIdx.x;
    const int base = blockIdx.x * 1024;
    const int b    = base >> 18;               // batch (constant per block)

    if (tid == 0) {
        s_bad = 0;
        const float* k = K + b * 9;
        float a = k[0], bb = k[1], c = k[2];
        float d = k[3], e  = k[4], f = k[5];
        float g = k[6], h  = k[7], i = k[8];
        float A  =  (e * i - f * h);
        float Bc = -(d * i - f * g);
        float Cc =  (d * h - e * g);
        float det = a * A + bb * Bc + c * Cc;
        float inv = 1.0f / det;
        sKi[0] = A * inv;
        sKi[1] = -(bb * i - c * h) * inv;
        sKi[2] =  (bb * f - c * e) * inv;
        sKi[3] = Bc * inv;
        sKi[4] =  (a * i - c * g) * inv;
        sKi[5] = -(a * f - c * d) * inv;
        sKi[6] = Cc * inv;
        sKi[7] = -(a * h - bb * g) * inv;
        sKi[8] =  (a * e - bb * d) * inv;
    }
    sT[tid] = T[b * (C_ * 16) + tid];
    if (tid < 9) sK[tid] = K[b * 9 + tid];
    __syncthreads();

    // Mask dtype sniff: 128 threads read first 512 bytes as u32.
    if (tid < 128) {
        unsigned wv = ((const unsigned*)masks)[tid];
        if (wv > 1u) atomicOr(&s_bad, 1);
    }
    __syncthreads();
    const bool mask_is_i32 = (s_bad == 0);

    const int idx = base + tid * 4;
    const int rem = idx & (HW_ - 1);
    const int v   = rem >> 9;
    const int u   = rem & (W_ - 1);

    const float4 d4 = *(const float4*)(depth + idx);
    const float  dd[4] = {d4.x, d4.y, d4.z, d4.w};

    // Last set channel per pixel; all 8 upper-channel loads batched.
    // NOTE: "any unresolved" test must be OR (-1 | x == -1), NOT AND.
    const long mbase = (long)b * (C_ * HW_) + rem;
    int cw[4] = {-1, -1, -1, -1};
    if (mask_is_i32) {
        const int* m = (const int*)masks;
        int4 a[8];
        #pragma unroll
        for (int j = 0; j < 8; ++j)
            a[j] = __ldg((const int4*)(m + mbase + (long)(8 + j) * HW_));
        #pragma unroll
        for (int j = 7; j >= 0; --j) {
            const int c = 8 + j;
            if (cw[0] < 0 && a[j].x) cw[0] = c;
            if (cw[1] < 0 && a[j].y) cw[1] = c;
            if (cw[2] < 0 && a[j].z) cw[2] = c;
            if (cw[3] < 0 && a[j].w) cw[3] = c;
        }
        if ((cw[0] | cw[1] | cw[2] | cw[3]) < 0) {   // any pixel unresolved
            #pragma unroll
            for (int j = 0; j < 8; ++j)
                a[j] = __ldg((const int4*)(m + mbase + (long)j * HW_));
            #pragma unroll
            for (int j = 7; j >= 0; --j) {
                if (cw[0] < 0 && a[j].x) cw[0] = j;
                if (cw[1] < 0 && a[j].y) cw[1] = j;
                if (cw[2] < 0 && a[j].z) cw[2] = j;
                if (cw[3] < 0 && a[j].w) cw[3] = j;
            }
        }
    } else {
        const unsigned char* mb = (const unsigned char*)masks;
        unsigned a[8];
        #pragma unroll
        for (int j = 0; j < 8; ++j)
            a[j] = __ldg((const unsigned*)(mb + mbase + (long)(8 + j) * HW_));
        #pragma unroll
        for (int j = 7; j >= 0; --j) {
            const int c = 8 + j;
            #pragma unroll
            for (int p = 0; p < 4; ++p)
                if (cw[p] < 0 && (a[j] & (0xffu << (8 * p)))) cw[p] = c;
        }
        if ((cw[0] | cw[1] | cw[2] | cw[3]) < 0) {   // any pixel unresolved
            #pragma unroll
            for (int j = 0; j < 8; ++j)
                a[j] = __ldg((const unsigned*)(mb + mbase + (long)j * HW_));
            #pragma unroll
            for (int j = 7; j >= 0; --j) {
                #pragma unroll
                for (int p = 0; p < 4; ++p)
                    if (cw[p] < 0 && (a[j] & (0xffu << (8 * p)))) cw[p] = j;
            }
        }
    }

    const float vf = (float)v;
    #pragma unroll
    for (int p = 0; p < 4; ++p) {
        const float uf = (float)(u + p);
        const float d  = dd[p];

        float x = (sKi[0] * uf + sKi[1] * vf + sKi[2]) * d;
        float y = (sKi[3] * uf + sKi[4] * vf + sKi[5]) * d;
        float z = (sKi[6] * uf + sKi[7] * vf + sKi[8]) * d;

        const int c = cw[p];
        if (c >= 0) {
            const float* Tm = &sT[c * 16];
            float tx = Tm[0]  * x + Tm[1]  * y + Tm[2]  * z + Tm[3];
            float ty = Tm[4]  * x + Tm[5]  * y + Tm[6]  * z + Tm[7];
            float tz = Tm[8]  * x + Tm[9]  * y + Tm[10] * z + Tm[11];
            float tw = Tm[12] * x + Tm[13] * y + Tm[14] * z + Tm[15];
            float inv = 1.0f / (tw + EPS_);
            x = tx * inv;
            y = ty * inv;
            z = tz * inv;
        }

        float phx = sK[0] * x + sK[1] * y + sK[2] * z;
        float phy = sK[3] * x + sK[4] * y + sK[5] * z;
        float phz = sK[6] * x + sK[7] * y + sK[8] * z;
        float invz = 1.0f / (phz + EPS_);
        float px = phx * invz;
        float py = phy * invz;

        int ui = (int)fminf(fmaxf(px, 0.0f), (float)(W_ - 1));
        int vi = (int)fminf(fmaxf(py, 0.0f), (float)(H_ - 1));

        unsigned long long pkt =
            ((unsigned long long)(unsigned)(rem + p + 1) << 32) |
            (unsigned long long)__float_as_uint(z);
        atomicMax(&g_scratch[b * HW_ + vi * W_ + ui], pkt);
    }
}

// ---------------------------------------------------------------------------
// Final: resolve scatter else passthrough depth; re-zero scratch.
// 4 px/thread (R2 configuration).
// ---------------------------------------------------------------------------
__global__ void __launch_bounds__(256)
final_kernel(const float* __restrict__ depth,
             float* __restrict__ out) {
    const int i4 = (blockIdx.x * 256 + threadIdx.x) * 4;

    ulonglong2 s01 = *(ulonglong2*)&g_scratch[i4];
    ulonglong2 s23 = *(ulonglong2*)&g_scratch[i4 + 2];
    const float4 dp = *(const float4*)(depth + i4);

    float4 o;
    o.x = s01.x ? __uint_as_float((unsigned)s01.x) : dp.x;
    o.y = s01.y ? __uint_as_float((unsigned)s01.y) : dp.y;
    o.z = s23.x ? __uint_as_float((unsigned)s23.x) : dp.z;
    o.w = s23.y ? __uint_as_float((unsigned)s23.y) : dp.w;
    *(float4*)(out + i4) = o;

    const ulonglong2 zz = {0ull, 0ull};
    *(ulonglong2*)&g_scratch[i4]     = zz;
    *(ulonglong2*)&g_scratch[i4 + 2] = zz;
}

extern "C" void kernel_launch(void* const* d_in, const int* in_sizes, int n_in,
                              void* d_out, int out_size) {
    const float* depth = (const float*)d_in[0];
    const float* K     = (const float*)d_in[1];
    const float* T     = (const float*)d_in[2];
    const void*  masks = d_in[3];
    float* out = (float*)d_out;

    main_kernel<<<NPIX_ / 1024, 256>>>(depth, K, T, masks);
    final_kernel<<<NPIX_ / 1024, 256>>>(depth, out);
}